// round 12
// baseline (speedup 1.0000x reference)
#include <cuda_runtime.h>
#include <cstdint>
#include <cfloat>

// Problem constants
#define N_PIX   16777216          // 16 * 1 * 1024 * 1024
#define NF4     4194304           // N_PIX / 4
#define RB      2048              // reduction blocks (32 KB each)
#define BINS    256
#define TILES   1024              // 16 images * 8 * 8
#define CLIPV   2560.0f           // max(int(40.0*16384//256),1)

// Scratch (device globals only — no allocations allowed)
__device__ float         g_pmin[RB];
__device__ float         g_pmax[RB];
__device__ double        g_psum[RB];
__device__ double        g_psq [RB];
__device__ float         g_AB[2];
__device__ unsigned int  g_ctr = 0;
__device__ unsigned char g_lut8[TILES * BINS];   // LUT values are exact ints 0..255

__device__ __forceinline__ unsigned int smem_u32(const void* p)
{
    unsigned int a;
    asm("{ .reg .u64 t; cvta.to.shared.u64 t, %1; cvt.u32.u64 %0, t; }"
        : "=r"(a) : "l"(p));
    return a;
}

__device__ __forceinline__ void mbar_wait_p0(unsigned int mb)
{
    asm volatile(
        "{\n\t"
        ".reg .pred p;\n\t"
        "WL_%=:\n\t"
        "mbarrier.try_wait.parity.acquire.cta.shared::cta.b64 p, [%0], 0, 0x989680;\n\t"
        "@p bra WD_%=;\n\t"
        "bra WL_%=;\n\t"
        "WD_%=:\n\t"
        "}" :: "r"(mb) : "memory");
}

// ---------------------------------------------------------------------------
// Kernel 1: streaming min/max/sum/sumsq via TMA BULK COPY. 2048 blocks x 256
// threads; ONE elected thread issues 8x cp.async.bulk (4 KB each, UBLKCP) into
// an 8-stage smem buffer — the fetch runs on the TMA path, off the warp
// instruction stream, so the chip streams at the LTS/DRAM cap instead of the
// per-warp LSU issue rate. 8 stages = 8 chunks: no reuse, no mid-loop syncs.
// Warp-shuffle epilogue; last block (fence + ticket) folds the 2048 partials,
// computes affine constants A,B (fp64 replica of the reference chain's
// normalize -> standardize -> normalize collapse), writes the y tail.
// ---------------------------------------------------------------------------
__global__ void __launch_bounds__(256) k_reduce(const float4* __restrict__ x,
                                                const int* __restrict__ y,
                                                float* __restrict__ tail_dst,
                                                int tail_n)
{
    __shared__ float4 sbuf[8 * 256];                       // 32 KB staging
    __shared__ __align__(8) unsigned long long mbar[8];
    __shared__ float  wmn[8], wmx[8];
    __shared__ double wss[8], wsq[8];

    int tid  = threadIdx.x;
    int lane = tid & 31;
    int wid  = tid >> 5;

    const float4* base = x + (size_t)blockIdx.x * 2048;    // 32 KB contiguous

    if (tid == 0) {
#pragma unroll
        for (int i = 0; i < 8; i++) {
            unsigned int mb = smem_u32(&mbar[i]);
            asm volatile("mbarrier.init.shared.b64 [%0], 1;" :: "r"(mb));
        }
    }
    __syncthreads();

    if (tid == 0) {
#pragma unroll
        for (int i = 0; i < 8; i++) {
            unsigned int mb  = smem_u32(&mbar[i]);
            unsigned int dst = smem_u32(&sbuf[i * 256]);
            asm volatile("mbarrier.arrive.expect_tx.shared.b64 _, [%0], %1;"
                         :: "r"(mb), "r"(4096u));
            asm volatile(
                "cp.async.bulk.shared::cluster.global.mbarrier::complete_tx::bytes "
                "[%0], [%1], %2, [%3];"
                :: "r"(dst), "l"(base + i * 256), "r"(4096u), "r"(mb) : "memory");
        }
    }

    float mn =  FLT_MAX, mx = -FLT_MAX;
    float s = 0.0f, q = 0.0f;
#pragma unroll
    for (int i = 0; i < 8; i++) {
        mbar_wait_p0(smem_u32(&mbar[i]));
        float4 v = sbuf[i * 256 + tid];
        mn = fminf(mn, fminf(fminf(v.x, v.y), fminf(v.z, v.w)));
        mx = fmaxf(mx, fmaxf(fmaxf(v.x, v.y), fmaxf(v.z, v.w)));
        s += (v.x + v.y) + (v.z + v.w);
        q += (v.x * v.x + v.y * v.y) + (v.z * v.z + v.w * v.w);
    }

    // warp shuffle reduction (fp32)
#pragma unroll
    for (int o = 16; o > 0; o >>= 1) {
        mn = fminf(mn, __shfl_xor_sync(0xFFFFFFFFu, mn, o));
        mx = fmaxf(mx, __shfl_xor_sync(0xFFFFFFFFu, mx, o));
        s += __shfl_xor_sync(0xFFFFFFFFu, s, o);
        q += __shfl_xor_sync(0xFFFFFFFFu, q, o);
    }
    if (lane == 0) {
        wmn[wid] = mn; wmx[wid] = mx;
        wss[wid] = (double)s; wsq[wid] = (double)q;
    }
    __syncthreads();

    if (wid == 0) {
        float  fmn = (lane < 8) ? wmn[lane] :  FLT_MAX;
        float  fmx = (lane < 8) ? wmx[lane] : -FLT_MAX;
        double ds  = (lane < 8) ? wss[lane] : 0.0;
        double dq  = (lane < 8) ? wsq[lane] : 0.0;
#pragma unroll
        for (int o = 4; o > 0; o >>= 1) {
            fmn = fminf(fmn, __shfl_xor_sync(0xFFFFFFFFu, fmn, o));
            fmx = fmaxf(fmx, __shfl_xor_sync(0xFFFFFFFFu, fmx, o));
            ds += __shfl_xor_sync(0xFFFFFFFFu, ds, o);
            dq += __shfl_xor_sync(0xFFFFFFFFu, dq, o);
        }
        if (lane == 0) {
            g_pmin[blockIdx.x] = fmn;
            g_pmax[blockIdx.x] = fmx;
            g_psum[blockIdx.x] = ds;
            g_psq [blockIdx.x] = dq;
        }
    }

    // ---- last-block-done: finalize + tail ----
    __shared__ bool is_last;
    __threadfence();
    if (tid == 0) {
        unsigned int ticket = atomicAdd(&g_ctr, 1u);
        is_last = (ticket == RB - 1);
    }
    __syncthreads();
    if (!is_last) return;

    __shared__ float  smn2[256], smx2[256];
    __shared__ double ss2[256], sq2[256];
    {
        float  lmn =  FLT_MAX, lmx = -FLT_MAX;
        double ls = 0.0, lq = 0.0;
#pragma unroll
        for (int i = 0; i < 8; i++) {
            int k = tid + i * 256;
            lmn = fminf(lmn, g_pmin[k]);
            lmx = fmaxf(lmx, g_pmax[k]);
            ls += g_psum[k];
            lq += g_psq[k];
        }
        smn2[tid] = lmn; smx2[tid] = lmx; ss2[tid] = ls; sq2[tid] = lq;
    }
    __syncthreads();
    for (int o = 128; o > 0; o >>= 1) {
        if (tid < o) {
            smn2[tid] = fminf(smn2[tid], smn2[tid + o]);
            smx2[tid] = fmaxf(smx2[tid], smx2[tid + o]);
            ss2[tid] += ss2[tid + o];
            sq2[tid] += sq2[tid + o];
        }
        __syncthreads();
    }
    if (tid == 0) {
        double mn2 = (double)smn2[0];
        double mx2 = (double)smx2[0];
        double span = mx2 - mn2;
        const double N = (double)N_PIX;
        double S = ss2[0], Q = sq2[0];
        double meanx = S / N;
        double varx  = (Q - S * S / N) / (N - 1.0);
        double mean1 = (meanx - mn2) / span;
        double std1  = sqrt(varx) / span;
        double zmin  = (0.0 - mean1) / std1;
        double zmax  = (1.0 - mean1) / std1;
        double zspan = zmax - zmin;
        double A = 1.0 / (span * std1 * zspan);
        double B = (((0.0 - mn2) / span - mean1) / std1 - zmin) / zspan;
        g_AB[0] = (float)A;
        g_AB[1] = (float)B;
        g_ctr = 0;                 // reset for next graph replay
    }
    // y tail: numeric float32 conversion (y is int32)
    if (tid < tail_n) tail_dst[tid] = (float)y[tid];
}

// ---------------------------------------------------------------------------
// Kernel 2: one 256-thread block per 128x128 tile. 8 warp-private
// sub-histograms (no bidx store), then clip -> scan -> residual -> LUT.
// x is L2-resident after k_reduce streamed it.
// ---------------------------------------------------------------------------
__global__ void __launch_bounds__(256) k_hist(const float* __restrict__ x)
{
    __shared__ unsigned int h[8][BINS];
    __shared__ float        cs[BINS];

    int t   = blockIdx.x;          // tile id: ((bc*8)+ti)*8+tj
    int tid = threadIdx.x;
#pragma unroll
    for (int k = 0; k < 8; k++) h[k][tid] = 0;
    __syncthreads();

    float A = g_AB[0], B = g_AB[1];

    int bc = t >> 6;
    int ti = (t >> 3) & 7;
    int tj = t & 7;
    int row0 = ti * 128;
    int col0 = tj * 128;
    int wsub = tid >> 5;           // warp-private sub-histogram

    const float4* xp = (const float4*)(x + ((size_t)bc << 20));

#pragma unroll
    for (int it = 0; it < 16; it++) {
        int row   = row0 + it * 8 + (tid >> 5);
        int cidx4 = (row << 8) + (col0 >> 2) + (tid & 31);  // float4 index
        float4 v  = xp[cidx4];
        int b0 = min(max((int)(fmaf(v.x, A, B) * 256.0f), 0), 255);
        int b1 = min(max((int)(fmaf(v.y, A, B) * 256.0f), 0), 255);
        int b2 = min(max((int)(fmaf(v.z, A, B) * 256.0f), 0), 255);
        int b3 = min(max((int)(fmaf(v.w, A, B) * 256.0f), 0), 255);
        atomicAdd(&h[wsub][b0], 1u);
        atomicAdd(&h[wsub][b1], 1u);
        atomicAdd(&h[wsub][b2], 1u);
        atomicAdd(&h[wsub][b3], 1u);
    }
    __syncthreads();

    unsigned int hv = 0;
#pragma unroll
    for (int k = 0; k < 8; k++) hv += h[k][tid];

    // clip + inclusive scan (Hillis-Steele) over 256 bins
    float v = fminf((float)hv, CLIPV);
    cs[tid] = v;
    __syncthreads();
#pragma unroll
    for (int off = 1; off < BINS; off <<= 1) {
        float add = (tid >= off) ? cs[tid - off] : 0.0f;
        __syncthreads();
        cs[tid] += add;
        __syncthreads();
    }
    float total = cs[BINS - 1];
    float resid = (16384.0f - total) * (1.0f / 256.0f);
    float lv = (cs[tid] + (float)(tid + 1) * resid) * (255.0f / 16384.0f);
    lv = floorf(fminf(fmaxf(lv, 0.0f), 255.0f));
    g_lut8[t * BINS + tid] = (unsigned char)lv;
}

// ---------------------------------------------------------------------------
// Kernel 3: bilinear LUT apply — recomputes the bin from x (byte-identical
// expression to k_hist; x is L2-resident), ONE LDS.32 per pixel, x[g] load
// software-pipelined one iteration ahead.
// ---------------------------------------------------------------------------
__device__ __forceinline__ float u8f(unsigned int packed, int sel)
{
    // byte -> float via exponent-bias trick: 0x4B0000vv = 8388608 + vv
    return __int_as_float(__byte_perm(packed, 0x4B000000, sel)) - 8388608.0f;
}

__global__ void __launch_bounds__(256) k_apply(const float4* __restrict__ x,
                                               float4* __restrict__ out)
{
    __shared__ unsigned int slut[8 * BINS];   // 8 KB

    int blk  = blockIdx.x;          // 0..2047
    int bc   = blk >> 7;            // image
    int seg  = blk & 127;           // 8-row segment
    int band = seg >> 3;            // 64-row band (0..15)
    int i0   = (band == 0) ? 0 : ((band - 1) >> 1);
    int i1   = min(i0 + 1, 7);

    const unsigned char* lb = g_lut8 + ((size_t)bc << 6) * BINS;
#pragma unroll
    for (int s = threadIdx.x; s < 8 * BINS; s += 256) {
        int j0 = s >> 8, b = s & 255;
        int j1 = min(j0 + 1, 7);
        unsigned int v00 = lb[(((i0 << 3) + j0) << 8) + b];
        unsigned int v10 = lb[(((i1 << 3) + j0) << 8) + b];
        unsigned int v01 = lb[(((i0 << 3) + j1) << 8) + b];
        unsigned int v11 = lb[(((i1 << 3) + j1) << 8) + b];
        slut[s] = v00 | (v10 << 8) | (v01 << 16) | (v11 << 24);
    }
    __syncthreads();

    float A = g_AB[0], B = g_AB[1];
    int tid = threadIdx.x;          // == col4 (float4 column), each it = 1 row

    // per-thread loop-invariant x-interpolation setup (4 pixels)
    float wx[4];
    int   jb[4];                    // (j0 << 8), ready to add bin
#pragma unroll
    for (int p = 0; p < 4; p++) {
        int   col = (tid << 2) + p;
        float gj  = fminf(fmaxf((col + 0.5f) * (1.0f / 128.0f) - 0.5f, 0.0f), 7.0f);
        int   j0  = (int)gj;
        wx[p] = gj - (float)j0;
        jb[p] = j0 << 8;
    }

    int row_base = seg << 3;                                // first row (8 rows)
    int f4_base  = (bc << 18) + (row_base << 8) + tid;      // float4 index

    float4 v = x[f4_base];                                  // prologue load
#pragma unroll
    for (int it = 0; it < 8; it++) {
        float4 vn;
        if (it < 7) vn = x[f4_base + ((it + 1) << 8)];      // prefetch next row

        int   row = row_base + it;
        float gi  = fminf(fmaxf((row + 0.5f) * (1.0f / 128.0f) - 0.5f, 0.0f), 7.0f);
        float wy  = gi - (float)i0;

        int bs[4];
        bs[0] = min(max((int)(fmaf(v.x, A, B) * 256.0f), 0), 255);
        bs[1] = min(max((int)(fmaf(v.y, A, B) * 256.0f), 0), 255);
        bs[2] = min(max((int)(fmaf(v.z, A, B) * 256.0f), 0), 255);
        bs[3] = min(max((int)(fmaf(v.w, A, B) * 256.0f), 0), 255);

        float r[4];
#pragma unroll
        for (int p = 0; p < 4; p++) {
            unsigned int packed = slut[jb[p] + bs[p]];
            float v00 = u8f(packed, 0x7440);
            float v10 = u8f(packed, 0x7441);
            float v01 = u8f(packed, 0x7442);
            float v11 = u8f(packed, 0x7443);
            float top = fmaf(wx[p], v01 - v00, v00);
            float bot = fmaf(wx[p], v11 - v10, v10);
            r[p] = fmaf(wy, bot - top, top) * (1.0f / 255.0f);
        }
        __stcs(&out[f4_base + (it << 8)], make_float4(r[0], r[1], r[2], r[3]));
        v = vn;
    }
}

extern "C" void kernel_launch(void* const* d_in, const int* in_sizes, int n_in,
                              void* d_out, int out_size)
{
    const float* x   = (const float*)d_in[0];
    const int*   y   = (n_in >= 2) ? (const int*)d_in[1] : nullptr;
    float*       out = (float*)d_out;

    int tail = out_size - N_PIX;
    if (tail < 0) tail = 0;

    k_reduce<<<RB, 256>>>((const float4*)x, y, out + N_PIX, tail);
    k_hist  <<<TILES, 256>>>(x);
    k_apply <<<2048, 256>>>((const float4*)x, (float4*)out);
}

// round 13
// speedup vs baseline: 1.0664x; 1.0664x over previous
#include <cuda_runtime.h>
#include <cstdint>
#include <cfloat>

// Problem constants
#define N_PIX   16777216          // 16 * 1 * 1024 * 1024
#define NF4     4194304           // N_PIX / 4
#define RB      1024              // reduction blocks
#define BINS    256
#define TILES   1024              // 16 images * 8 * 8
#define CLIPV   2560.0f           // max(int(40.0*16384//256),1)

// Scratch (device globals only — no allocations allowed)
__device__ float         g_pmin[RB];
__device__ float         g_pmax[RB];
__device__ double        g_psum[RB];
__device__ double        g_psq [RB];
__device__ float         g_AB[2];     // A*256, B*256 (bin-ready affine)
__device__ unsigned int  g_ctr = 0;
__device__ unsigned char g_lut8[TILES * BINS];   // LUT values are exact ints 0..255

__device__ __forceinline__ unsigned int smem_u32(const void* p)
{
    unsigned int a;
    asm("{ .reg .u64 t; cvta.to.shared.u64 t, %1; cvt.u32.u64 %0, t; }"
        : "=r"(a) : "l"(p));
    return a;
}

// ---------------------------------------------------------------------------
// Kernel 1 (R11-proven): streaming min/max/sum/sumsq. 1024 blocks x 256 thr x
// 16 chunks, 8-stage cp.async ring — loads stream while older chunks reduce.
// Warp-shuffle epilogue; last block folds partials, computes A*256/B*256,
// writes the y tail.
// ---------------------------------------------------------------------------
__global__ void __launch_bounds__(256) k_reduce(const float4* __restrict__ x,
                                                const int* __restrict__ y,
                                                float* __restrict__ tail_dst,
                                                int tail_n)
{
    __shared__ float4 sbuf[8 * 256];        // 32 KB ring (8 stages)
    __shared__ float  wmn[8], wmx[8];
    __shared__ double wss[8], wsq[8];

    int tid  = threadIdx.x;
    int lane = tid & 31;
    int wid  = tid >> 5;
    int t    = blockIdx.x * 256 + tid;

    float mn =  FLT_MAX, mx = -FLT_MAX;
    float s = 0.0f, q = 0.0f;

#define ISSUE(c) { \
        unsigned int dst = smem_u32(&sbuf[((c) & 7) * 256 + tid]); \
        const float4* src = x + t + (c) * (RB * 256); \
        asm volatile("cp.async.cg.shared.global [%0], [%1], 16;" :: "r"(dst), "l"(src)); \
        asm volatile("cp.async.commit_group;"); }

#define CONSUME(c, W) { \
        asm volatile("cp.async.wait_group " #W ";" ::: "memory"); \
        float4 v = sbuf[((c) & 7) * 256 + tid]; \
        mn = fminf(mn, fminf(fminf(v.x, v.y), fminf(v.z, v.w))); \
        mx = fmaxf(mx, fmaxf(fmaxf(v.x, v.y), fmaxf(v.z, v.w))); \
        s += (v.x + v.y) + (v.z + v.w); \
        q += (v.x * v.x + v.y * v.y) + (v.z * v.z + v.w * v.w); }

    ISSUE(0) ISSUE(1) ISSUE(2) ISSUE(3) ISSUE(4) ISSUE(5) ISSUE(6) ISSUE(7)
    CONSUME(0, 7)  ISSUE(8)
    CONSUME(1, 7)  ISSUE(9)
    CONSUME(2, 7)  ISSUE(10)
    CONSUME(3, 7)  ISSUE(11)
    CONSUME(4, 7)  ISSUE(12)
    CONSUME(5, 7)  ISSUE(13)
    CONSUME(6, 7)  ISSUE(14)
    CONSUME(7, 7)  ISSUE(15)
    CONSUME(8, 7)
    CONSUME(9, 6)
    CONSUME(10, 5)
    CONSUME(11, 4)
    CONSUME(12, 3)
    CONSUME(13, 2)
    CONSUME(14, 1)
    CONSUME(15, 0)
#undef ISSUE
#undef CONSUME

#pragma unroll
    for (int o = 16; o > 0; o >>= 1) {
        mn = fminf(mn, __shfl_xor_sync(0xFFFFFFFFu, mn, o));
        mx = fmaxf(mx, __shfl_xor_sync(0xFFFFFFFFu, mx, o));
        s += __shfl_xor_sync(0xFFFFFFFFu, s, o);
        q += __shfl_xor_sync(0xFFFFFFFFu, q, o);
    }
    if (lane == 0) {
        wmn[wid] = mn; wmx[wid] = mx;
        wss[wid] = (double)s; wsq[wid] = (double)q;
    }
    __syncthreads();

    if (wid == 0) {
        float  fmn = (lane < 8) ? wmn[lane] :  FLT_MAX;
        float  fmx = (lane < 8) ? wmx[lane] : -FLT_MAX;
        double ds  = (lane < 8) ? wss[lane] : 0.0;
        double dq  = (lane < 8) ? wsq[lane] : 0.0;
#pragma unroll
        for (int o = 4; o > 0; o >>= 1) {
            fmn = fminf(fmn, __shfl_xor_sync(0xFFFFFFFFu, fmn, o));
            fmx = fmaxf(fmx, __shfl_xor_sync(0xFFFFFFFFu, fmx, o));
            ds += __shfl_xor_sync(0xFFFFFFFFu, ds, o);
            dq += __shfl_xor_sync(0xFFFFFFFFu, dq, o);
        }
        if (lane == 0) {
            g_pmin[blockIdx.x] = fmn;
            g_pmax[blockIdx.x] = fmx;
            g_psum[blockIdx.x] = ds;
            g_psq [blockIdx.x] = dq;
        }
    }

    // ---- last-block-done: finalize + tail ----
    __shared__ bool is_last;
    __threadfence();
    if (tid == 0) {
        unsigned int ticket = atomicAdd(&g_ctr, 1u);
        is_last = (ticket == RB - 1);
    }
    __syncthreads();
    if (!is_last) return;

    __shared__ float  smn2[256], smx2[256];
    __shared__ double ss2[256], sq2[256];
    {
        float  lmn =  FLT_MAX, lmx = -FLT_MAX;
        double ls = 0.0, lq = 0.0;
#pragma unroll
        for (int i = 0; i < 4; i++) {
            int k = tid + i * 256;
            lmn = fminf(lmn, g_pmin[k]);
            lmx = fmaxf(lmx, g_pmax[k]);
            ls += g_psum[k];
            lq += g_psq[k];
        }
        smn2[tid] = lmn; smx2[tid] = lmx; ss2[tid] = ls; sq2[tid] = lq;
    }
    __syncthreads();
    for (int o = 128; o > 0; o >>= 1) {
        if (tid < o) {
            smn2[tid] = fminf(smn2[tid], smn2[tid + o]);
            smx2[tid] = fmaxf(smx2[tid], smx2[tid + o]);
            ss2[tid] += ss2[tid + o];
            sq2[tid] += sq2[tid + o];
        }
        __syncthreads();
    }
    if (tid == 0) {
        double mn2 = (double)smn2[0];
        double mx2 = (double)smx2[0];
        double span = mx2 - mn2;
        const double N = (double)N_PIX;
        double S = ss2[0], Q = sq2[0];
        double meanx = S / N;
        double varx  = (Q - S * S / N) / (N - 1.0);
        double mean1 = (meanx - mn2) / span;
        double std1  = sqrt(varx) / span;
        double zmin  = (0.0 - mean1) / std1;
        double zmax  = (1.0 - mean1) / std1;
        double zspan = zmax - zmin;
        double A = 1.0 / (span * std1 * zspan);
        double B = (((0.0 - mn2) / span - mean1) / std1 - zmin) / zspan;
        g_AB[0] = (float)(A * 256.0);   // bin-ready
        g_AB[1] = (float)(B * 256.0);
        g_ctr = 0;                 // reset for next graph replay
    }
    // y tail: numeric float32 conversion (y is int32)
    if (tid < tail_n) tail_dst[tid] = (float)y[tid];
}

// bin = clamp((int)fmaf(v, A256, B256), 0, 255) — MUST be identical in
// k_hist and k_apply so LUT construction and LUT lookup agree.
__device__ __forceinline__ int binof(float v, float A256, float B256)
{
    return min(max((int)fmaf(v, A256, B256), 0), 255);
}

// ---------------------------------------------------------------------------
// Kernel 2: one 256-thread block per 128x128 tile. 8 warp-private
// sub-histograms, then clip -> scan -> residual -> LUT. x is L2-resident.
// ---------------------------------------------------------------------------
__global__ void __launch_bounds__(256) k_hist(const float* __restrict__ x)
{
    __shared__ unsigned int h[8][BINS];
    __shared__ float        cs[BINS];

    int t   = blockIdx.x;          // tile id: ((bc*8)+ti)*8+tj
    int tid = threadIdx.x;
#pragma unroll
    for (int k = 0; k < 8; k++) h[k][tid] = 0;
    __syncthreads();

    float A = g_AB[0], B = g_AB[1];

    int bc = t >> 6;
    int ti = (t >> 3) & 7;
    int tj = t & 7;
    int row0 = ti * 128;
    int col0 = tj * 128;
    int wsub = tid >> 5;

    const float4* xp = (const float4*)(x + ((size_t)bc << 20));

#pragma unroll
    for (int it = 0; it < 16; it++) {
        int row   = row0 + it * 8 + (tid >> 5);
        int cidx4 = (row << 8) + (col0 >> 2) + (tid & 31);
        float4 v  = xp[cidx4];
        atomicAdd(&h[wsub][binof(v.x, A, B)], 1u);
        atomicAdd(&h[wsub][binof(v.y, A, B)], 1u);
        atomicAdd(&h[wsub][binof(v.z, A, B)], 1u);
        atomicAdd(&h[wsub][binof(v.w, A, B)], 1u);
    }
    __syncthreads();

    unsigned int hv = 0;
#pragma unroll
    for (int k = 0; k < 8; k++) hv += h[k][tid];

    float v = fminf((float)hv, CLIPV);
    cs[tid] = v;
    __syncthreads();
#pragma unroll
    for (int off = 1; off < BINS; off <<= 1) {
        float add = (tid >= off) ? cs[tid - off] : 0.0f;
        __syncthreads();
        cs[tid] += add;
        __syncthreads();
    }
    float total = cs[BINS - 1];
    float resid = (16384.0f - total) * (1.0f / 256.0f);
    float lv = (cs[tid] + (float)(tid + 1) * resid) * (255.0f / 16384.0f);
    lv = floorf(fminf(fmaxf(lv, 0.0f), 255.0f));
    g_lut8[t * BINS + tid] = (unsigned char)lv;
}

// ---------------------------------------------------------------------------
// Kernel 3: bilinear LUT apply — bin recomputed from x (identical binof),
// ONE LDS.32 per pixel, biased byte->float with the bias subtracted only in
// the fma addend (differences are bias-free), x load pipelined one row ahead.
// ---------------------------------------------------------------------------
#define BIASF 8388608.0f

__device__ __forceinline__ float u8biased(unsigned int packed, int sel)
{
    // 0x4B0000vv = 8388608 + vv (biased; exact)
    return __int_as_float(__byte_perm(packed, 0x4B000000, sel));
}

__global__ void __launch_bounds__(256) k_apply(const float4* __restrict__ x,
                                               float4* __restrict__ out)
{
    __shared__ unsigned int slut[8 * BINS];   // 8 KB

    int blk  = blockIdx.x;          // 0..2047
    int bc   = blk >> 7;            // image
    int seg  = blk & 127;           // 8-row segment
    int band = seg >> 3;            // 64-row band (0..15)
    int i0   = (band == 0) ? 0 : ((band - 1) >> 1);
    int i1   = min(i0 + 1, 7);

    const unsigned char* lb = g_lut8 + ((size_t)bc << 6) * BINS;
#pragma unroll
    for (int s = threadIdx.x; s < 8 * BINS; s += 256) {
        int j0 = s >> 8, b = s & 255;
        int j1 = min(j0 + 1, 7);
        unsigned int v00 = lb[(((i0 << 3) + j0) << 8) + b];
        unsigned int v10 = lb[(((i1 << 3) + j0) << 8) + b];
        unsigned int v01 = lb[(((i0 << 3) + j1) << 8) + b];
        unsigned int v11 = lb[(((i1 << 3) + j1) << 8) + b];
        slut[s] = v00 | (v10 << 8) | (v01 << 16) | (v11 << 24);
    }
    __syncthreads();

    float A = g_AB[0], B = g_AB[1];
    int tid = threadIdx.x;          // == col4; each iteration = one image row

    float wx[4];
    int   jb[4];
#pragma unroll
    for (int p = 0; p < 4; p++) {
        int   col = (tid << 2) + p;
        float gj  = fminf(fmaxf((col + 0.5f) * (1.0f / 128.0f) - 0.5f, 0.0f), 7.0f);
        int   j0  = (int)gj;
        wx[p] = gj - (float)j0;
        jb[p] = j0 << 8;
    }

    int row_base = seg << 3;
    int f4_base  = (bc << 18) + (row_base << 8) + tid;

    float4 v = x[f4_base];
#pragma unroll
    for (int it = 0; it < 8; it++) {
        float4 vn;
        if (it < 7) vn = x[f4_base + ((it + 1) << 8)];

        int   row = row_base + it;
        float gi  = fminf(fmaxf((row + 0.5f) * (1.0f / 128.0f) - 0.5f, 0.0f), 7.0f);
        float wy  = gi - (float)i0;

        int bs[4];
        bs[0] = binof(v.x, A, B);
        bs[1] = binof(v.y, A, B);
        bs[2] = binof(v.z, A, B);
        bs[3] = binof(v.w, A, B);

        float r[4];
#pragma unroll
        for (int p = 0; p < 4; p++) {
            unsigned int packed = slut[jb[p] + bs[p]];
            float b00 = u8biased(packed, 0x7440);   // v00 + C
            float b10 = u8biased(packed, 0x7441);   // v10 + C
            float b01 = u8biased(packed, 0x7442);   // v01 + C
            float b11 = u8biased(packed, 0x7443);   // v11 + C
            // diffs are exact (bias cancels); subtract bias only in addends
            float top = fmaf(wx[p], b01 - b00, b00 - BIASF);
            float bot = fmaf(wx[p], b11 - b10, b10 - BIASF);
            r[p] = fmaf(wy, bot - top, top) * (1.0f / 255.0f);
        }
        __stcs(&out[f4_base + (it << 8)], make_float4(r[0], r[1], r[2], r[3]));
        v = vn;
    }
}

extern "C" void kernel_launch(void* const* d_in, const int* in_sizes, int n_in,
                              void* d_out, int out_size)
{
    const float* x   = (const float*)d_in[0];
    const int*   y   = (n_in >= 2) ? (const int*)d_in[1] : nullptr;
    float*       out = (float*)d_out;

    int tail = out_size - N_PIX;
    if (tail < 0) tail = 0;

    k_reduce<<<RB, 256>>>((const float4*)x, y, out + N_PIX, tail);
    k_hist  <<<TILES, 256>>>(x);
    k_apply <<<2048, 256>>>((const float4*)x, (float4*)out);
}

// round 14
// speedup vs baseline: 1.0702x; 1.0036x over previous
#include <cuda_runtime.h>
#include <cstdint>
#include <cfloat>

// Problem constants
#define N_PIX   16777216          // 16 * 1 * 1024 * 1024
#define NF4     4194304           // N_PIX / 4
#define RB      1024              // reduction blocks
#define BINS    256
#define TILES   1024              // 16 images * 8 * 8
#define CLIPV   2560.0f           // max(int(40.0*16384//256),1)
#define FGRID   1024              // fused kernel grid
#define NITEMS  2048              // 1024 hist + 1024 apply

// Scratch (device globals only — no allocations allowed)
__device__ float         g_pmin[RB];
__device__ float         g_pmax[RB];
__device__ double        g_psum[RB];
__device__ double        g_psq [RB];
__device__ float         g_AB[2];     // A*256, B*256 (bin-ready affine)
__device__ unsigned int  g_ctr = 0;
__device__ unsigned char g_lut8[TILES * BINS];
__device__ unsigned int  g_qhead = 0;          // work-queue head
__device__ unsigned int  g_qdone = 0;          // exit tickets
__device__ unsigned int  g_rowdone[128];       // (image, tile-row) -> tiles done

__device__ __forceinline__ unsigned int smem_u32(const void* p)
{
    unsigned int a;
    asm("{ .reg .u64 t; cvta.to.shared.u64 t, %1; cvt.u32.u64 %0, t; }"
        : "=r"(a) : "l"(p));
    return a;
}

// ---------------------------------------------------------------------------
// Kernel 1 (R11/R13-proven): streaming min/max/sum/sumsq, 8-stage cp.async
// ring; warp-shuffle epilogue; last block folds partials, computes A*256 and
// B*256 (fp64 replica of the reference chain), writes the y tail.
// ---------------------------------------------------------------------------
__global__ void __launch_bounds__(256) k_reduce(const float4* __restrict__ x,
                                                const int* __restrict__ y,
                                                float* __restrict__ tail_dst,
                                                int tail_n)
{
    __shared__ float4 sbuf[8 * 256];        // 32 KB ring (8 stages)
    __shared__ float  wmn[8], wmx[8];
    __shared__ double wss[8], wsq[8];

    int tid  = threadIdx.x;
    int lane = tid & 31;
    int wid  = tid >> 5;
    int t    = blockIdx.x * 256 + tid;

    float mn =  FLT_MAX, mx = -FLT_MAX;
    float s = 0.0f, q = 0.0f;

#define ISSUE(c) { \
        unsigned int dst = smem_u32(&sbuf[((c) & 7) * 256 + tid]); \
        const float4* src = x + t + (c) * (RB * 256); \
        asm volatile("cp.async.cg.shared.global [%0], [%1], 16;" :: "r"(dst), "l"(src)); \
        asm volatile("cp.async.commit_group;"); }

#define CONSUME(c, W) { \
        asm volatile("cp.async.wait_group " #W ";" ::: "memory"); \
        float4 v = sbuf[((c) & 7) * 256 + tid]; \
        mn = fminf(mn, fminf(fminf(v.x, v.y), fminf(v.z, v.w))); \
        mx = fmaxf(mx, fmaxf(fmaxf(v.x, v.y), fmaxf(v.z, v.w))); \
        s += (v.x + v.y) + (v.z + v.w); \
        q += (v.x * v.x + v.y * v.y) + (v.z * v.z + v.w * v.w); }

    ISSUE(0) ISSUE(1) ISSUE(2) ISSUE(3) ISSUE(4) ISSUE(5) ISSUE(6) ISSUE(7)
    CONSUME(0, 7)  ISSUE(8)
    CONSUME(1, 7)  ISSUE(9)
    CONSUME(2, 7)  ISSUE(10)
    CONSUME(3, 7)  ISSUE(11)
    CONSUME(4, 7)  ISSUE(12)
    CONSUME(5, 7)  ISSUE(13)
    CONSUME(6, 7)  ISSUE(14)
    CONSUME(7, 7)  ISSUE(15)
    CONSUME(8, 7)
    CONSUME(9, 6)
    CONSUME(10, 5)
    CONSUME(11, 4)
    CONSUME(12, 3)
    CONSUME(13, 2)
    CONSUME(14, 1)
    CONSUME(15, 0)
#undef ISSUE
#undef CONSUME

#pragma unroll
    for (int o = 16; o > 0; o >>= 1) {
        mn = fminf(mn, __shfl_xor_sync(0xFFFFFFFFu, mn, o));
        mx = fmaxf(mx, __shfl_xor_sync(0xFFFFFFFFu, mx, o));
        s += __shfl_xor_sync(0xFFFFFFFFu, s, o);
        q += __shfl_xor_sync(0xFFFFFFFFu, q, o);
    }
    if (lane == 0) {
        wmn[wid] = mn; wmx[wid] = mx;
        wss[wid] = (double)s; wsq[wid] = (double)q;
    }
    __syncthreads();

    if (wid == 0) {
        float  fmn = (lane < 8) ? wmn[lane] :  FLT_MAX;
        float  fmx = (lane < 8) ? wmx[lane] : -FLT_MAX;
        double ds  = (lane < 8) ? wss[lane] : 0.0;
        double dq  = (lane < 8) ? wsq[lane] : 0.0;
#pragma unroll
        for (int o = 4; o > 0; o >>= 1) {
            fmn = fminf(fmn, __shfl_xor_sync(0xFFFFFFFFu, fmn, o));
            fmx = fmaxf(fmx, __shfl_xor_sync(0xFFFFFFFFu, fmx, o));
            ds += __shfl_xor_sync(0xFFFFFFFFu, ds, o);
            dq += __shfl_xor_sync(0xFFFFFFFFu, dq, o);
        }
        if (lane == 0) {
            g_pmin[blockIdx.x] = fmn;
            g_pmax[blockIdx.x] = fmx;
            g_psum[blockIdx.x] = ds;
            g_psq [blockIdx.x] = dq;
        }
    }

    // ---- last-block-done: finalize + tail ----
    __shared__ bool is_last;
    __threadfence();
    if (tid == 0) {
        unsigned int ticket = atomicAdd(&g_ctr, 1u);
        is_last = (ticket == RB - 1);
    }
    __syncthreads();
    if (!is_last) return;

    __shared__ float  smn2[256], smx2[256];
    __shared__ double ss2[256], sq2[256];
    {
        float  lmn =  FLT_MAX, lmx = -FLT_MAX;
        double ls = 0.0, lq = 0.0;
#pragma unroll
        for (int i = 0; i < 4; i++) {
            int k = tid + i * 256;
            lmn = fminf(lmn, g_pmin[k]);
            lmx = fmaxf(lmx, g_pmax[k]);
            ls += g_psum[k];
            lq += g_psq[k];
        }
        smn2[tid] = lmn; smx2[tid] = lmx; ss2[tid] = ls; sq2[tid] = lq;
    }
    __syncthreads();
    for (int o = 128; o > 0; o >>= 1) {
        if (tid < o) {
            smn2[tid] = fminf(smn2[tid], smn2[tid + o]);
            smx2[tid] = fmaxf(smx2[tid], smx2[tid + o]);
            ss2[tid] += ss2[tid + o];
            sq2[tid] += sq2[tid + o];
        }
        __syncthreads();
    }
    if (tid == 0) {
        double mn2 = (double)smn2[0];
        double mx2 = (double)smx2[0];
        double span = mx2 - mn2;
        const double N = (double)N_PIX;
        double S = ss2[0], Q = sq2[0];
        double meanx = S / N;
        double varx  = (Q - S * S / N) / (N - 1.0);
        double mean1 = (meanx - mn2) / span;
        double std1  = sqrt(varx) / span;
        double zmin  = (0.0 - mean1) / std1;
        double zmax  = (1.0 - mean1) / std1;
        double zspan = zmax - zmin;
        double A = 1.0 / (span * std1 * zspan);
        double B = (((0.0 - mn2) / span - mean1) / std1 - zmin) / zspan;
        g_AB[0] = (float)(A * 256.0);   // bin-ready
        g_AB[1] = (float)(B * 256.0);
        g_ctr = 0;                 // reset for next graph replay
    }
    if (tid < tail_n) tail_dst[tid] = (float)y[tid];   // y is int32
}

// bin = clamp((int)fmaf(v, A256, B256), 0, 255) — identical in hist & apply.
__device__ __forceinline__ int binof(float v, float A256, float B256)
{
    return min(max((int)fmaf(v, A256, B256), 0), 255);
}

#define BIASF 8388608.0f
__device__ __forceinline__ float u8biased(unsigned int packed, int sel)
{
    return __int_as_float(__byte_perm(packed, 0x4B000000, sel));
}

// ---------------------------------------------------------------------------
// hist item: tile t — 8 warp-private sub-histograms, clip/scan/residual/LUT,
// then publish tile-row completion (fence + counter).
// ---------------------------------------------------------------------------
__device__ void do_hist(int t, const float* __restrict__ x,
                        unsigned int* h, float* cs, int tid)
{
#pragma unroll
    for (int k = 0; k < 8; k++) h[k * BINS + tid] = 0;
    __syncthreads();

    float A = g_AB[0], B = g_AB[1];
    int bc = t >> 6;
    int ti = (t >> 3) & 7;
    int tj = t & 7;
    int row0 = ti * 128;
    int col0 = tj * 128;
    unsigned int* hw = h + (tid >> 5) * BINS;

    const float4* xp = (const float4*)(x + ((size_t)bc << 20));
#pragma unroll
    for (int it = 0; it < 16; it++) {
        int row   = row0 + it * 8 + (tid >> 5);
        int cidx4 = (row << 8) + (col0 >> 2) + (tid & 31);
        float4 v  = xp[cidx4];
        atomicAdd(&hw[binof(v.x, A, B)], 1u);
        atomicAdd(&hw[binof(v.y, A, B)], 1u);
        atomicAdd(&hw[binof(v.z, A, B)], 1u);
        atomicAdd(&hw[binof(v.w, A, B)], 1u);
    }
    __syncthreads();

    unsigned int hv = 0;
#pragma unroll
    for (int k = 0; k < 8; k++) hv += h[k * BINS + tid];

    float v = fminf((float)hv, CLIPV);
    cs[tid] = v;
    __syncthreads();
#pragma unroll
    for (int off = 1; off < BINS; off <<= 1) {
        float add = (tid >= off) ? cs[tid - off] : 0.0f;
        __syncthreads();
        cs[tid] += add;
        __syncthreads();
    }
    float total = cs[BINS - 1];
    float resid = (16384.0f - total) * (1.0f / 256.0f);
    float lv = (cs[tid] + (float)(tid + 1) * resid) * (255.0f / 16384.0f);
    lv = floorf(fminf(fmaxf(lv, 0.0f), 255.0f));
    g_lut8[t * BINS + tid] = (unsigned char)lv;

    __threadfence();          // each thread's LUT byte visible device-wide
    __syncthreads();
    if (tid == 0) atomicAdd(&g_rowdone[bc * 8 + ti], 1u);
}

// ---------------------------------------------------------------------------
// apply item: (bc, band, quarter) — wait for the two needed LUT tile-rows,
// build packed slut, bilinear-apply 16 rows (ONE LDS.32 per pixel).
// ---------------------------------------------------------------------------
__device__ void do_apply(int a, const float4* __restrict__ x,
                         float4* __restrict__ out,
                         unsigned int* slut, int tid)
{
    int bc   = a >> 6;
    int band = (a >> 2) & 15;
    int sub  = a & 3;
    int i0   = (band == 0) ? 0 : ((band - 1) >> 1);
    int i1   = min(i0 + 1, 7);

    if (tid == 0) {
        while (atomicAdd(&g_rowdone[bc * 8 + i0], 0u) < 8u) __nanosleep(64);
        while (atomicAdd(&g_rowdone[bc * 8 + i1], 0u) < 8u) __nanosleep(64);
    }
    __syncthreads();
    __threadfence();          // acquire: order LUT reads after counter observe

    const unsigned char* lb = g_lut8 + ((size_t)bc << 6) * BINS;
#pragma unroll
    for (int s = tid; s < 8 * BINS; s += 256) {
        int j0 = s >> 8, b = s & 255;
        int j1 = min(j0 + 1, 7);
        unsigned int v00 = __ldcg(&lb[(((i0 << 3) + j0) << 8) + b]);
        unsigned int v10 = __ldcg(&lb[(((i1 << 3) + j0) << 8) + b]);
        unsigned int v01 = __ldcg(&lb[(((i0 << 3) + j1) << 8) + b]);
        unsigned int v11 = __ldcg(&lb[(((i1 << 3) + j1) << 8) + b]);
        slut[s] = v00 | (v10 << 8) | (v01 << 16) | (v11 << 24);
    }
    __syncthreads();

    float A = g_AB[0], B = g_AB[1];

    float wx[4];
    int   jb[4];
#pragma unroll
    for (int p = 0; p < 4; p++) {
        int   col = (tid << 2) + p;
        float gj  = fminf(fmaxf((col + 0.5f) * (1.0f / 128.0f) - 0.5f, 0.0f), 7.0f);
        int   j0  = (int)gj;
        wx[p] = gj - (float)j0;
        jb[p] = j0 << 8;
    }

    int row_base = band * 64 + sub * 16;
    int f4_base  = (bc << 18) + (row_base << 8) + tid;

    float4 v = x[f4_base];
#pragma unroll
    for (int it = 0; it < 16; it++) {
        float4 vn;
        if (it < 15) vn = x[f4_base + ((it + 1) << 8)];

        int   row = row_base + it;
        float gi  = fminf(fmaxf((row + 0.5f) * (1.0f / 128.0f) - 0.5f, 0.0f), 7.0f);
        float wy  = gi - (float)i0;

        int bs[4];
        bs[0] = binof(v.x, A, B);
        bs[1] = binof(v.y, A, B);
        bs[2] = binof(v.z, A, B);
        bs[3] = binof(v.w, A, B);

        float r[4];
#pragma unroll
        for (int p = 0; p < 4; p++) {
            unsigned int packed = slut[jb[p] + bs[p]];
            float b00 = u8biased(packed, 0x7440);
            float b10 = u8biased(packed, 0x7441);
            float b01 = u8biased(packed, 0x7442);
            float b11 = u8biased(packed, 0x7443);
            float top = fmaf(wx[p], b01 - b00, b00 - BIASF);
            float bot = fmaf(wx[p], b11 - b10, b10 - BIASF);
            r[p] = fmaf(wy, bot - top, top) * (1.0f / 255.0f);
        }
        __stcs(&out[f4_base + (it << 8)], make_float4(r[0], r[1], r[2], r[3]));
        v = vn;
    }
}

// ---------------------------------------------------------------------------
// Kernel 2: fused hist+apply, dynamic work queue. Items 0..1023 = hist tiles,
// 1024..2047 = apply quarter-bands. Queue order assigns all hist items before
// any apply item -> apply spins only on in-flight hist work -> deadlock-free.
// Last-exiting block resets all queue state for the next graph replay.
// ---------------------------------------------------------------------------
__global__ void __launch_bounds__(256) k_fused(const float* __restrict__ x,
                                               float4* __restrict__ out)
{
    __shared__ unsigned int hbuf[8 * BINS];   // 8 KB: hist sub-hists / slut
    __shared__ float        cs[BINS];
    __shared__ int          s_item;

    int tid = threadIdx.x;

    for (;;) {
        if (tid == 0) s_item = (int)atomicAdd(&g_qhead, 1u);
        __syncthreads();
        int item = s_item;
        __syncthreads();
        if (item >= NITEMS) break;

        if (item < 1024) do_hist(item, x, hbuf, cs, tid);
        else             do_apply(item - 1024, (const float4*)x, out, hbuf, tid);
    }

    if (tid == 0) {
        __threadfence();
        unsigned int tk = atomicAdd(&g_qdone, 1u);
        if (tk == FGRID - 1) {          // last exiter: all items complete
            g_qhead = 0;
            g_qdone = 0;
            for (int i = 0; i < 128; i++) g_rowdone[i] = 0;
        }
    }
}

extern "C" void kernel_launch(void* const* d_in, const int* in_sizes, int n_in,
                              void* d_out, int out_size)
{
    const float* x   = (const float*)d_in[0];
    const int*   y   = (n_in >= 2) ? (const int*)d_in[1] : nullptr;
    float*       out = (float*)d_out;

    int tail = out_size - N_PIX;
    if (tail < 0) tail = 0;

    k_reduce<<<RB, 256>>>((const float4*)x, y, out + N_PIX, tail);
    k_fused <<<FGRID, 256>>>(x, (float4*)out);
}